// round 2
// baseline (speedup 1.0000x reference)
#include <cuda_runtime.h>
#include <cuda_bf16.h>

// Welford running mean/variance over batch dim of x: (B, C, H, W), B=256, CHW=262144.
// float4-vectorized: each thread owns 4 consecutive spatial positions.
// Output layout (float32, concatenated):
//   [0, B*CHW)               : x passthrough
//   [B*CHW, +CHW)            : m
//   [+CHW, +2CHW)            : s
//   [+2CHW, +3CHW)           : neuron_nonzero (int -> float)
//   [B*CHW+3*CHW]            : n_samples + B

__global__ void __launch_bounds__(128) welford_kernel_v4(
    const float4* __restrict__ x,
    const float4* __restrict__ m_in,
    const float4* __restrict__ s_in,
    const int4*   __restrict__ nn_in,
    const int*    __restrict__ n_in,
    float*        __restrict__ out,
    int B, int CHW4)   // CHW4 = CHW / 4
{
    int p4 = blockIdx.x * blockDim.x + threadIdx.x;
    if (p4 >= CHW4) return;

    float4 m  = m_in[p4];
    float4 s  = s_in[p4];
    int4   nn = nn_in[p4];
    const int n0 = n_in[0];

    const float4* xp = x + p4;
    float4*       op = reinterpret_cast<float4*>(out) + p4;

    #pragma unroll 4
    for (int b = 0; b < B; ++b) {
        float4 xv = __ldcs(&xp[(size_t)b * CHW4]);
        __stcs(&op[(size_t)b * CHW4], xv);        // passthrough (streaming)

        float inv = __fdividef(1.0f, (float)(n0 + b + 1));

        nn.x += (xv.x != 0.0f);
        nn.y += (xv.y != 0.0f);
        nn.z += (xv.z != 0.0f);
        nn.w += (xv.w != 0.0f);

        float om;
        om = m.x; m.x += (xv.x - m.x) * inv; s.x += (xv.x - m.x) * (xv.x - om);
        om = m.y; m.y += (xv.y - m.y) * inv; s.y += (xv.y - m.y) * (xv.y - om);
        om = m.z; m.z += (xv.z - m.z) * inv; s.z += (xv.z - m.z) * (xv.z - om);
        om = m.w; m.w += (xv.w - m.w) * inv; s.w += (xv.w - m.w) * (xv.w - om);
    }

    const size_t CHW = (size_t)CHW4 * 4;
    float4* out4 = reinterpret_cast<float4*>(out);
    const size_t base4 = (size_t)B * CHW4;        // in float4 units

    out4[base4 + p4]            = m;
    out4[base4 + CHW4 + p4]     = s;
    out4[base4 + 2 * (size_t)CHW4 + p4] =
        make_float4((float)nn.x, (float)nn.y, (float)nn.z, (float)nn.w);
    if (p4 == 0) {
        out[(size_t)B * CHW + 3 * CHW] = (float)(n0 + B);
    }
}

extern "C" void kernel_launch(void* const* d_in, const int* in_sizes, int n_in,
                              void* d_out, int out_size)
{
    const float4* x  = (const float4*)d_in[0];
    const float4* m  = (const float4*)d_in[1];
    const float4* s  = (const float4*)d_in[2];
    const int4*   nn = (const int4*)d_in[3];
    const int*    n  = (const int*)d_in[4];
    float* out = (float*)d_out;

    const int CHW = in_sizes[1];          // 262144
    const int B   = in_sizes[0] / CHW;    // 256
    const int CHW4 = CHW / 4;             // 65536

    const int threads = 128;
    const int blocks = (CHW4 + threads - 1) / threads;  // 512
    welford_kernel_v4<<<blocks, threads>>>(x, m, s, nn, n, out, B, CHW4);
}

// round 3
// speedup vs baseline: 1.1081x; 1.1081x over previous
#include <cuda_runtime.h>
#include <cuda_bf16.h>

// Welford running mean/variance over batch dim of x: (B, C, H, W), B=256, CHW=262144.
// float2-vectorized: each thread owns 2 consecutive spatial positions across all B.
// 131,072 threads -> with unroll 8, ~8 MB of loads in flight (latency-hiding floor ~2.4 MB).
// Output layout (float32, concatenated):
//   [0, B*CHW)     : x passthrough
//   [+0, +CHW)     : m
//   [+CHW, +2CHW)  : s
//   [+2CHW, +3CHW) : neuron_nonzero (int -> float)
//   [last]         : n_samples + B

__global__ void __launch_bounds__(256) welford_kernel_v2(
    const float2* __restrict__ x,
    const float2* __restrict__ m_in,
    const float2* __restrict__ s_in,
    const int2*   __restrict__ nn_in,
    const int*    __restrict__ n_in,
    float*        __restrict__ out,
    int B, int CHW2)   // CHW2 = CHW / 2
{
    int p2 = blockIdx.x * blockDim.x + threadIdx.x;
    if (p2 >= CHW2) return;

    float2 m  = m_in[p2];
    float2 s  = s_in[p2];
    int2   nn = nn_in[p2];
    const int n0 = n_in[0];

    const float2* xp = x + p2;
    float2*       op = reinterpret_cast<float2*>(out) + p2;

    #pragma unroll 8
    for (int b = 0; b < B; ++b) {
        float2 xv = __ldcs(&xp[(size_t)b * CHW2]);
        __stcs(&op[(size_t)b * CHW2], xv);        // passthrough (streaming)

        float inv = __fdividef(1.0f, (float)(n0 + b + 1));

        nn.x += (xv.x != 0.0f);
        nn.y += (xv.y != 0.0f);

        float om;
        om = m.x; m.x += (xv.x - m.x) * inv; s.x += (xv.x - m.x) * (xv.x - om);
        om = m.y; m.y += (xv.y - m.y) * inv; s.y += (xv.y - m.y) * (xv.y - om);
    }

    const size_t CHW = (size_t)CHW2 * 2;
    float2* out2 = reinterpret_cast<float2*>(out);
    const size_t base2 = (size_t)B * CHW2;        // in float2 units

    out2[base2 + p2]                    = m;
    out2[base2 + (size_t)CHW2 + p2]     = s;
    out2[base2 + 2 * (size_t)CHW2 + p2] = make_float2((float)nn.x, (float)nn.y);
    if (p2 == 0) {
        out[(size_t)B * CHW + 3 * CHW] = (float)(n0 + B);
    }
}

extern "C" void kernel_launch(void* const* d_in, const int* in_sizes, int n_in,
                              void* d_out, int out_size)
{
    const float2* x  = (const float2*)d_in[0];
    const float2* m  = (const float2*)d_in[1];
    const float2* s  = (const float2*)d_in[2];
    const int2*   nn = (const int2*)d_in[3];
    const int*    n  = (const int*)d_in[4];
    float* out = (float*)d_out;

    const int CHW = in_sizes[1];          // 262144
    const int B   = in_sizes[0] / CHW;    // 256
    const int CHW2 = CHW / 2;             // 131072

    const int threads = 256;
    const int blocks = (CHW2 + threads - 1) / threads;  // 512
    welford_kernel_v2<<<blocks, threads>>>(x, m, s, nn, n, out, B, CHW2);
}

// round 4
// speedup vs baseline: 1.8217x; 1.6440x over previous
#include <cuda_runtime.h>
#include <cuda_bf16.h>

// Welford running mean/variance over batch dim of x: (B, C, H, W), B=256, CHW=262144.
// 262,144 scalar threads (one per spatial position) — proven warp count from R1.
// NEW: each thread runs TWO independent Welford streams over the two batch halves
// (doubling loads-in-flight per warp), merged exactly with Chan's formula.
//
// Output layout (float32, concatenated):
//   [0, B*CHW)     : x passthrough
//   [+0, +CHW)     : m
//   [+CHW, +2CHW)  : s
//   [+2CHW, +3CHW) : neuron_nonzero (int -> float)
//   [last]         : n_samples + B

__global__ void __launch_bounds__(256) welford_kernel_2s(
    const float* __restrict__ x,
    const float* __restrict__ m_in,
    const float* __restrict__ s_in,
    const int*   __restrict__ nn_in,
    const int*   __restrict__ n_in,
    float*       __restrict__ out,
    int B, int CHW)
{
    int p = blockIdx.x * blockDim.x + threadIdx.x;
    if (p >= CHW) return;

    const int H  = B >> 1;              // 128
    const int n0 = n_in[0];

    // Stream A: continues the input state over b = 0..H-1
    float mA = m_in[p];
    float sA = s_in[p];
    int   nnA = nn_in[p];

    // Stream B: standalone Welford from zero over b = H..B-1
    float mB = 0.0f, sB = 0.0f;
    int   nnB = 0;

    const float* xpA = x + p;
    const float* xpB = x + p + (size_t)H * CHW;
    float*       opA = out + p;
    float*       opB = out + p + (size_t)H * CHW;

    #pragma unroll 4
    for (int b = 0; b < H; ++b) {
        float xa = xpA[(size_t)b * CHW];
        float xb = xpB[(size_t)b * CHW];
        opA[(size_t)b * CHW] = xa;          // passthrough
        opB[(size_t)b * CHW] = xb;

        nnA += (xa != 0.0f);
        nnB += (xb != 0.0f);

        float invA = __fdividef(1.0f, (float)(n0 + b + 1));
        float invB = __fdividef(1.0f, (float)(b + 1));

        float om;
        om = mA; mA += (xa - mA) * invA; sA += (xa - mA) * (xa - om);
        om = mB; mB += (xb - mB) * invB; sB += (xb - mB) * (xb - om);
    }

    // Chan merge: A holds n0+H samples of weight, B holds H samples.
    float nAf = (float)(n0 + H);
    float nBf = (float)H;
    float nTf = nAf + nBf;
    float invT = __fdividef(1.0f, nTf);
    float d  = mB - mA;
    float m  = mA + d * (nBf * invT);
    float s  = sA + sB + d * d * (nAf * nBf * invT);
    int   nn = nnA + nnB;

    size_t base = (size_t)B * (size_t)CHW;
    out[base + p]                    = m;
    out[base + (size_t)CHW + p]      = s;
    out[base + 2 * (size_t)CHW + p]  = (float)nn;
    if (p == 0) {
        out[base + 3 * (size_t)CHW] = (float)(n0 + B);
    }
}

extern "C" void kernel_launch(void* const* d_in, const int* in_sizes, int n_in,
                              void* d_out, int out_size)
{
    const float* x  = (const float*)d_in[0];
    const float* m  = (const float*)d_in[1];
    const float* s  = (const float*)d_in[2];
    const int*   nn = (const int*)d_in[3];
    const int*   n  = (const int*)d_in[4];
    float* out = (float*)d_out;

    const int CHW = in_sizes[1];          // 262144
    const int B   = in_sizes[0] / CHW;    // 256

    const int threads = 256;
    const int blocks = (CHW + threads - 1) / threads;  // 1024
    welford_kernel_2s<<<blocks, threads>>>(x, m, s, nn, n, out, B, CHW);
}